// round 1
// baseline (speedup 1.0000x reference)
#include <cuda_runtime.h>

#define TPB 256

// softplus: stable, MUFU-based: max(x,0) + log(1 + exp(-|x|))
__device__ __forceinline__ float softplus_f(float x) {
    float e = __expf(-fabsf(x));        // FMUL(log2e, -|x|) + MUFU.EX2
    return fmaxf(x, 0.0f) + __logf(1.0f + e);  // FADD + MUFU.LG2 + FFMA
}

// Weight SMEM layout (floats):
//   [0..63]    W_in padded to 8x8 (cols 6,7 = 0)
//   [64..71]   b_in
//   [72..135]  W1   [136..143] b1
//   [144..207] W2   [208..215] b2
//   [216..279] W3   [280..287] b3
//   [288..351] W4   [352..359] b4
//   [360..479] W_out (15 rows x 8)
//   [480..494] b_out
__global__ __launch_bounds__(TPB)
void poisson_bivector_kernel(
    const float* __restrict__ x,
    const float* __restrict__ Win, const float* __restrict__ bin,
    const float* __restrict__ W1,  const float* __restrict__ b1,
    const float* __restrict__ W2,  const float* __restrict__ b2,
    const float* __restrict__ W3,  const float* __restrict__ b3,
    const float* __restrict__ W4,  const float* __restrict__ b4,
    const float* __restrict__ Wout,const float* __restrict__ bout,
    float* __restrict__ out, int npts)
{
    __shared__ float s_w[496];
    __shared__ float s_x[TPB * 6];
    __shared__ float s_o[TPB * 36];

    const int t = threadIdx.x;
    const int base = blockIdx.x * TPB;
    const int cnt = min(TPB, npts - base);

    // ---- stage weights (once per block) ----
    {
        // W_in padded to 8x8
        for (int i = t; i < 64; i += TPB) {
            int r = i >> 3, c = i & 7;
            s_w[i] = (c < 6) ? Win[r * 6 + c] : 0.0f;
        }
        if (t < 8)  s_w[64 + t]  = bin[t];
        for (int i = t; i < 64; i += TPB) s_w[72 + i]  = W1[i];
        if (t < 8)  s_w[136 + t] = b1[t];
        for (int i = t; i < 64; i += TPB) s_w[144 + i] = W2[i];
        if (t < 8)  s_w[208 + t] = b2[t];
        for (int i = t; i < 64; i += TPB) s_w[216 + i] = W3[i];
        if (t < 8)  s_w[280 + t] = b3[t];
        for (int i = t; i < 64; i += TPB) s_w[288 + i] = W4[i];
        if (t < 8)  s_w[352 + t] = b4[t];
        for (int i = t; i < 120; i += TPB) s_w[360 + i] = Wout[i];
        if (t < 15) s_w[480 + t] = bout[t];
    }

    // ---- stage x: cnt*6 contiguous floats, vectorized ----
    {
        const float* xg = x + (size_t)base * 6;
        int nfl = cnt * 6;
        int nf4 = nfl >> 2;
        const float4* xg4 = (const float4*)xg;  // base*24B: 16B-aligned (base mult of 256)
        float4* sx4 = (float4*)s_x;
        for (int i = t; i < nf4; i += TPB) sx4[i] = xg4[i];
        for (int i = (nf4 << 2) + t; i < nfl; i += TPB) s_x[i] = xg[i];
    }
    __syncthreads();

    // ---- compute (one point per thread) ----
    if (t < cnt) {
        float a[8];
#pragma unroll
        for (int c = 0; c < 6; c++) a[c] = s_x[t * 6 + c];
        a[6] = 0.0f; a[7] = 0.0f;

        const int woff[5] = {0, 72, 144, 216, 288};
        const int boff[5] = {64, 136, 208, 280, 352};
#pragma unroll
        for (int l = 0; l < 5; l++) {
            const float4* W = (const float4*)(s_w + woff[l]);
            const float*  b = s_w + boff[l];
            float na[8];
#pragma unroll
            for (int o = 0; o < 8; o++) {
                float4 w0 = W[2 * o], w1 = W[2 * o + 1];
                float acc = b[o];
                acc = fmaf(w0.x, a[0], acc); acc = fmaf(w0.y, a[1], acc);
                acc = fmaf(w0.z, a[2], acc); acc = fmaf(w0.w, a[3], acc);
                acc = fmaf(w1.x, a[4], acc); acc = fmaf(w1.y, a[5], acc);
                acc = fmaf(w1.z, a[6], acc); acc = fmaf(w1.w, a[7], acc);
                na[o] = softplus_f(acc);
            }
#pragma unroll
            for (int o = 0; o < 8; o++) a[o] = na[o];
        }

        // output layer: ut[15] = W_out @ a + b_out  (no activation)
        float u[15];
        {
            const float4* W = (const float4*)(s_w + 360);
            const float*  b = s_w + 480;
#pragma unroll
            for (int o = 0; o < 15; o++) {
                float4 w0 = W[2 * o], w1 = W[2 * o + 1];
                float acc = b[o];
                acc = fmaf(w0.x, a[0], acc); acc = fmaf(w0.y, a[1], acc);
                acc = fmaf(w0.z, a[2], acc); acc = fmaf(w0.w, a[3], acc);
                acc = fmaf(w1.x, a[4], acc); acc = fmaf(w1.y, a[5], acc);
                acc = fmaf(w1.z, a[6], acc); acc = fmaf(w1.w, a[7], acc);
                u[o] = acc;
            }
        }

        // Assemble 6x6 antisymmetric matrix (row-major) directly as 9 float4s.
        // Row r: L[r][c] = u[k] for c>r (row-major triu order), -u[k] for c<r, 0 diag.
        float4* so = (float4*)(s_o + t * 36);  // stride 36 floats: conflict-free STS.128
        so[0] = make_float4( 0.0f,  u[0],   u[1],   u[2]);
        so[1] = make_float4( u[3],  u[4],  -u[0],   0.0f);
        so[2] = make_float4( u[5],  u[6],   u[7],   u[8]);
        so[3] = make_float4(-u[1], -u[5],   0.0f,   u[9]);
        so[4] = make_float4( u[10], u[11], -u[2],  -u[6]);
        so[5] = make_float4(-u[9],  0.0f,   u[12],  u[13]);
        so[6] = make_float4(-u[3], -u[7],  -u[10], -u[12]);
        so[7] = make_float4( 0.0f,  u[14], -u[4],  -u[8]);
        so[8] = make_float4(-u[11],-u[13], -u[14],  0.0f);
    }
    __syncthreads();

    // ---- coalesced copy out: cnt*36 contiguous floats as float4 ----
    {
        float4* og = (float4*)(out + (size_t)base * 36);  // base*144B: 16B-aligned
        const float4* so4 = (const float4*)s_o;
        int no4 = cnt * 9;
        for (int i = t; i < no4; i += TPB) og[i] = so4[i];
    }
}

extern "C" void kernel_launch(void* const* d_in, const int* in_sizes, int n_in,
                              void* d_out, int out_size) {
    const float* x    = (const float*)d_in[0];
    const float* Win  = (const float*)d_in[1];
    const float* bin  = (const float*)d_in[2];
    const float* W1   = (const float*)d_in[3];
    const float* b1   = (const float*)d_in[4];
    const float* W2   = (const float*)d_in[5];
    const float* b2   = (const float*)d_in[6];
    const float* W3   = (const float*)d_in[7];
    const float* b3   = (const float*)d_in[8];
    const float* W4   = (const float*)d_in[9];
    const float* b4   = (const float*)d_in[10];
    const float* Wout = (const float*)d_in[11];
    const float* bout = (const float*)d_in[12];
    float* out = (float*)d_out;

    int npts = in_sizes[0] / 6;
    int blocks = (npts + TPB - 1) / TPB;
    poisson_bivector_kernel<<<blocks, TPB>>>(
        x, Win, bin, W1, b1, W2, b2, W3, b3, W4, b4, Wout, bout, out, npts);
}

// round 5
// speedup vs baseline: 1.2700x; 1.2700x over previous
#include <cuda_runtime.h>

#define TPB 128
#define PPT 4   // points per thread

// softplus: stable, MUFU-based: max(x,0) + log(1 + exp(-|x|))
__device__ __forceinline__ float softplus_f(float x) {
    float e = __expf(-fabsf(x));               // FMUL + MUFU.EX2
    return fmaxf(x, 0.0f) + __logf(1.0f + e);  // FMNMX + FADD + MUFU.LG2 + FMUL + FADD
}

// Weight SMEM layout (floats):
//   [0..63]    W_in padded to 8x8 (cols 6,7 = 0)
//   [64..71]   b_in
//   [72..135]  W1   [136..143] b1
//   [144..207] W2   [208..215] b2
//   [216..279] W3   [280..287] b3
//   [288..351] W4   [352..359] b4
//   [360..479] W_out (15 rows x 8)
//   [480..494] b_out
__global__ __launch_bounds__(TPB)
void poisson_bivector_kernel(
    const float* __restrict__ x,
    const float* __restrict__ Win, const float* __restrict__ bin,
    const float* __restrict__ W1,  const float* __restrict__ b1,
    const float* __restrict__ W2,  const float* __restrict__ b2,
    const float* __restrict__ W3,  const float* __restrict__ b3,
    const float* __restrict__ W4,  const float* __restrict__ b4,
    const float* __restrict__ Wout,const float* __restrict__ bout,
    float* __restrict__ out, int npts)
{
    __shared__ float s_w[496];
    __shared__ float s_o[TPB * 36];   // one 128-pt group staged at a time

    const int t = threadIdx.x;
    const int base = blockIdx.x * (TPB * PPT);

    // ---- stage weights (once per block) ----
    {
        for (int i = t; i < 64; i += TPB) {
            int r = i >> 3, c = i & 7;
            s_w[i] = (c < 6) ? Win[r * 6 + c] : 0.0f;
        }
        if (t < 8)  s_w[64 + t]  = bin[t];
        for (int i = t; i < 64; i += TPB) s_w[72 + i]  = W1[i];
        if (t < 8)  s_w[136 + t] = b1[t];
        for (int i = t; i < 64; i += TPB) s_w[144 + i] = W2[i];
        if (t < 8)  s_w[208 + t] = b2[t];
        for (int i = t; i < 64; i += TPB) s_w[216 + i] = W3[i];
        if (t < 8)  s_w[280 + t] = b3[t];
        for (int i = t; i < 64; i += TPB) s_w[288 + i] = W4[i];
        if (t < 8)  s_w[352 + t] = b4[t];
        for (int i = t; i < 120; i += TPB) s_w[360 + i] = Wout[i];
        if (t < 15) s_w[480 + t] = bout[t];
    }
    __syncthreads();

    // ---- load x for all 4 point-groups straight to registers (3x LDG.64 each) ----
    float a[PPT][8];
#pragma unroll
    for (int g = 0; g < PPT; g++) {
        int pt = base + g * TPB + t;
        if (pt < npts) {
            const float2* xp = (const float2*)(x + (size_t)pt * 6);
            float2 v0 = xp[0], v1 = xp[1], v2 = xp[2];
            a[g][0] = v0.x; a[g][1] = v0.y; a[g][2] = v1.x;
            a[g][3] = v1.y; a[g][4] = v2.x; a[g][5] = v2.y;
        } else {
            a[g][0] = a[g][1] = a[g][2] = a[g][3] = a[g][4] = a[g][5] = 0.0f;
        }
        a[g][6] = 0.0f; a[g][7] = 0.0f;
    }

    // ---- 5 hidden layers, weight LDS shared 4-ways ----
    const int woff[5] = {0, 72, 144, 216, 288};
    const int boff[5] = {64, 136, 208, 280, 352};
#pragma unroll
    for (int l = 0; l < 5; l++) {
        const float4* W = (const float4*)(s_w + woff[l]);
        const float*  b = s_w + boff[l];
        float na[PPT][8];
#pragma unroll
        for (int o = 0; o < 8; o++) {
            float4 w0 = W[2 * o], w1 = W[2 * o + 1];
            float bo = b[o];
#pragma unroll
            for (int g = 0; g < PPT; g++) {
                float acc = bo;
                acc = fmaf(w0.x, a[g][0], acc); acc = fmaf(w0.y, a[g][1], acc);
                acc = fmaf(w0.z, a[g][2], acc); acc = fmaf(w0.w, a[g][3], acc);
                acc = fmaf(w1.x, a[g][4], acc); acc = fmaf(w1.y, a[g][5], acc);
                acc = fmaf(w1.z, a[g][6], acc); acc = fmaf(w1.w, a[g][7], acc);
                na[g][o] = softplus_f(acc);
            }
        }
#pragma unroll
        for (int g = 0; g < PPT; g++)
#pragma unroll
            for (int o = 0; o < 8; o++) a[g][o] = na[g][o];
    }

    // ---- output layer in pairs (Wout LDS shared 2-ways), staged copyout per group ----
#pragma unroll
    for (int p = 0; p < PPT / 2; p++) {
        const int g0 = 2 * p, g1 = 2 * p + 1;
        float u0[15], u1[15];
        {
            const float4* W = (const float4*)(s_w + 360);
            const float*  b = s_w + 480;
#pragma unroll
            for (int o = 0; o < 15; o++) {
                float4 w0 = W[2 * o], w1 = W[2 * o + 1];
                float bo = b[o];
                float A = bo, B = bo;
                A = fmaf(w0.x, a[g0][0], A); B = fmaf(w0.x, a[g1][0], B);
                A = fmaf(w0.y, a[g0][1], A); B = fmaf(w0.y, a[g1][1], B);
                A = fmaf(w0.z, a[g0][2], A); B = fmaf(w0.z, a[g1][2], B);
                A = fmaf(w0.w, a[g0][3], A); B = fmaf(w0.w, a[g1][3], B);
                A = fmaf(w1.x, a[g0][4], A); B = fmaf(w1.x, a[g1][4], B);
                A = fmaf(w1.y, a[g0][5], A); B = fmaf(w1.y, a[g1][5], B);
                A = fmaf(w1.z, a[g0][6], A); B = fmaf(w1.z, a[g1][6], B);
                A = fmaf(w1.w, a[g0][7], A); B = fmaf(w1.w, a[g1][7], B);
                u0[o] = A; u1[o] = B;
            }
        }

#pragma unroll
        for (int h = 0; h < 2; h++) {
            const float* u = (h == 0) ? u0 : u1;
            const int g = 2 * p + h;

            __syncthreads();   // previous copyout of s_o finished
            // Assemble 6x6 antisymmetric matrix as 9 float4s (stride 36 floats: conflict-free STS.128)
            float4* so = (float4*)(s_o + t * 36);
            so[0] = make_float4( 0.0f,  u[0],   u[1],   u[2]);
            so[1] = make_float4( u[3],  u[4],  -u[0],   0.0f);
            so[2] = make_float4( u[5],  u[6],   u[7],   u[8]);
            so[3] = make_float4(-u[1], -u[5],   0.0f,   u[9]);
            so[4] = make_float4( u[10], u[11], -u[2],  -u[6]);
            so[5] = make_float4(-u[9],  0.0f,   u[12],  u[13]);
            so[6] = make_float4(-u[3], -u[7],  -u[10], -u[12]);
            so[7] = make_float4( 0.0f,  u[14], -u[4],  -u[8]);
            so[8] = make_float4(-u[11],-u[13], -u[14],  0.0f);
            __syncthreads();   // stores visible block-wide

            // coalesced copy out: cg*36 contiguous floats as float4
            int gb = base + g * TPB;
            int cg = npts - gb;
            if (cg > TPB) cg = TPB;
            if (cg < 0) cg = 0;
            float4* og = (float4*)(out + (size_t)gb * 36);
            const float4* so4 = (const float4*)s_o;
            for (int i = t; i < cg * 9; i += TPB) og[i] = so4[i];
        }
    }
}

extern "C" void kernel_launch(void* const* d_in, const int* in_sizes, int n_in,
                              void* d_out, int out_size) {
    const float* x    = (const float*)d_in[0];
    const float* Win  = (const float*)d_in[1];
    const float* bin  = (const float*)d_in[2];
    const float* W1   = (const float*)d_in[3];
    const float* b1   = (const float*)d_in[4];
    const float* W2   = (const float*)d_in[5];
    const float* b2   = (const float*)d_in[6];
    const float* W3   = (const float*)d_in[7];
    const float* b3   = (const float*)d_in[8];
    const float* W4   = (const float*)d_in[9];
    const float* b4   = (const float*)d_in[10];
    const float* Wout = (const float*)d_in[11];
    const float* bout = (const float*)d_in[12];
    float* out = (float*)d_out;

    int npts = in_sizes[0] / 6;
    int ptsPerBlock = TPB * PPT;
    int blocks = (npts + ptsPerBlock - 1) / ptsPerBlock;
    poisson_bivector_kernel<<<blocks, TPB>>>(
        x, Win, bin, W1, b1, W2, b2, W3, b3, W4, b4, Wout, bout, out, npts);
}

// round 6
// speedup vs baseline: 1.3430x; 1.0575x over previous
#include <cuda_runtime.h>

#define TPB 128
#define PPT 4   // points per thread, processed as 2 f32x2 pairs
typedef unsigned long long u64;

// ---- packed f32x2 helpers (sm_100+ PTX) ----
__device__ __forceinline__ u64 pk(float lo, float hi) {
    u64 r; asm("mov.b64 %0, {%1, %2};" : "=l"(r) : "f"(lo), "f"(hi)); return r;
}
__device__ __forceinline__ void upk(float& lo, float& hi, u64 v) {
    asm("mov.b64 {%0, %1}, %2;" : "=f"(lo), "=f"(hi) : "l"(v));
}
__device__ __forceinline__ u64 ffma2(u64 a, u64 b, u64 c) {
    u64 d; asm("fma.rn.f32x2 %0, %1, %2, %3;" : "=l"(d) : "l"(a), "l"(b), "l"(c)); return d;
}

// softplus: stable, MUFU-based: max(x,0) + log(1 + exp(-|x|))
__device__ __forceinline__ float softplus_f(float x) {
    float e = __expf(-fabsf(x));
    return fmaxf(x, 0.0f) + __logf(1.0f + e);
}
__device__ __forceinline__ u64 softplus2(u64 v) {
    float lo, hi; upk(lo, hi, v);
    return pk(softplus_f(lo), softplus_f(hi));
}

// Duplicated-weight SMEM layout (floats), every weight/bias w stored as (w,w):
//   [0..96)    W_in  8 rows x 6 dup (12 floats/row)
//   [96..112)  b_in dup
//   [112+l*144 .. ) for l=0..3 : W{1..4} 8 rows x 8 dup (16/row) + 16 bias dup
//   [688..928) W_out 15 rows x 8 dup
//   [928..958) b_out dup
__global__ __launch_bounds__(TPB)
void poisson_bivector_kernel(
    const float* __restrict__ x,
    const float* __restrict__ Win, const float* __restrict__ bin,
    const float* __restrict__ W1,  const float* __restrict__ b1,
    const float* __restrict__ W2,  const float* __restrict__ b2,
    const float* __restrict__ W3,  const float* __restrict__ b3,
    const float* __restrict__ W4,  const float* __restrict__ b4,
    const float* __restrict__ Wout,const float* __restrict__ bout,
    float* __restrict__ out, int npts)
{
    __shared__ __align__(16) float s_w[960];
    __shared__ __align__(16) float s_o[2][TPB * 36];  // double-buffered staging

    const int t = threadIdx.x;
    const int base = blockIdx.x * (TPB * PPT);

    // ---- stage duplicated weights (once per block) ----
    for (int i = t; i < 48; i += TPB) {           // W_in 8x6
        int r = i / 6, c = i % 6; float v = Win[i];
        s_w[r * 12 + 2 * c] = v; s_w[r * 12 + 2 * c + 1] = v;
    }
    if (t < 8) { float v = bin[t]; s_w[96 + 2 * t] = v; s_w[97 + 2 * t] = v; }
    {
        const float* Ws[4] = {W1, W2, W3, W4};
        const float* Bs[4] = {b1, b2, b3, b4};
#pragma unroll
        for (int l = 0; l < 4; l++) {
            int wb = 112 + l * 144;
            for (int i = t; i < 64; i += TPB) {
                float v = Ws[l][i];
                s_w[wb + 2 * i] = v; s_w[wb + 2 * i + 1] = v;
            }
            if (t < 8) { float v = Bs[l][t]; s_w[wb + 128 + 2 * t] = v; s_w[wb + 129 + 2 * t] = v; }
        }
    }
    for (int i = t; i < 120; i += TPB) {          // W_out 15x8
        float v = Wout[i];
        s_w[688 + 2 * i] = v; s_w[689 + 2 * i] = v;
    }
    if (t < 15) { float v = bout[t]; s_w[928 + 2 * t] = v; s_w[929 + 2 * t] = v; }
    __syncthreads();

    // ---- load x, pack pairs: pair p = points (base+2p*TPB+t, base+(2p+1)*TPB+t) ----
    u64 a2[2][8];
#pragma unroll
    for (int p = 0; p < 2; p++) {
        float xa[6], xb[6];
        int p0 = base + (2 * p) * TPB + t;
        int p1 = p0 + TPB;
        if (p0 < npts) {
            const float2* xp = (const float2*)(x + (size_t)p0 * 6);
            float2 v0 = xp[0], v1 = xp[1], v2 = xp[2];
            xa[0]=v0.x; xa[1]=v0.y; xa[2]=v1.x; xa[3]=v1.y; xa[4]=v2.x; xa[5]=v2.y;
        } else { xa[0]=xa[1]=xa[2]=xa[3]=xa[4]=xa[5]=0.0f; }
        if (p1 < npts) {
            const float2* xp = (const float2*)(x + (size_t)p1 * 6);
            float2 v0 = xp[0], v1 = xp[1], v2 = xp[2];
            xb[0]=v0.x; xb[1]=v0.y; xb[2]=v1.x; xb[3]=v1.y; xb[4]=v2.x; xb[5]=v2.y;
        } else { xb[0]=xb[1]=xb[2]=xb[3]=xb[4]=xb[5]=0.0f; }
#pragma unroll
        for (int c = 0; c < 6; c++) a2[p][c] = pk(xa[c], xb[c]);
        a2[p][6] = 0ull; a2[p][7] = 0ull;
    }

    // ---- input layer: 6 real inputs ----
    {
        const ulonglong2* W = (const ulonglong2*)(s_w);
        const u64* Bv = (const u64*)(s_w + 96);
        u64 n0[8], n1[8];
#pragma unroll
        for (int o = 0; o < 8; o++) {
            ulonglong2 q0 = W[3*o], q1 = W[3*o+1], q2 = W[3*o+2];
            u64 bo = Bv[o];
            u64 A = bo, B = bo;
            A = ffma2(q0.x, a2[0][0], A);  B = ffma2(q0.x, a2[1][0], B);
            A = ffma2(q0.y, a2[0][1], A);  B = ffma2(q0.y, a2[1][1], B);
            A = ffma2(q1.x, a2[0][2], A);  B = ffma2(q1.x, a2[1][2], B);
            A = ffma2(q1.y, a2[0][3], A);  B = ffma2(q1.y, a2[1][3], B);
            A = ffma2(q2.x, a2[0][4], A);  B = ffma2(q2.x, a2[1][4], B);
            A = ffma2(q2.y, a2[0][5], A);  B = ffma2(q2.y, a2[1][5], B);
            n0[o] = softplus2(A); n1[o] = softplus2(B);
        }
#pragma unroll
        for (int o = 0; o < 8; o++) { a2[0][o] = n0[o]; a2[1][o] = n1[o]; }
    }

    // ---- 4 hidden layers 8x8 ----
#pragma unroll
    for (int l = 0; l < 4; l++) {
        const ulonglong2* W = (const ulonglong2*)(s_w + 112 + l * 144);
        const u64* Bv = (const u64*)(s_w + 112 + l * 144 + 128);
        u64 n0[8], n1[8];
#pragma unroll
        for (int o = 0; o < 8; o++) {
            ulonglong2 q0 = W[4*o], q1 = W[4*o+1], q2 = W[4*o+2], q3 = W[4*o+3];
            u64 bo = Bv[o];
            u64 A = bo, B = bo;
            A = ffma2(q0.x, a2[0][0], A);  B = ffma2(q0.x, a2[1][0], B);
            A = ffma2(q0.y, a2[0][1], A);  B = ffma2(q0.y, a2[1][1], B);
            A = ffma2(q1.x, a2[0][2], A);  B = ffma2(q1.x, a2[1][2], B);
            A = ffma2(q1.y, a2[0][3], A);  B = ffma2(q1.y, a2[1][3], B);
            A = ffma2(q2.x, a2[0][4], A);  B = ffma2(q2.x, a2[1][4], B);
            A = ffma2(q2.y, a2[0][5], A);  B = ffma2(q2.y, a2[1][5], B);
            A = ffma2(q3.x, a2[0][6], A);  B = ffma2(q3.x, a2[1][6], B);
            A = ffma2(q3.y, a2[0][7], A);  B = ffma2(q3.y, a2[1][7], B);
            n0[o] = softplus2(A); n1[o] = softplus2(B);
        }
#pragma unroll
        for (int o = 0; o < 8; o++) { a2[0][o] = n0[o]; a2[1][o] = n1[o]; }
    }

    // ---- output layer per pair + staged TMA bulk-store copyout ----
#pragma unroll
    for (int p = 0; p < 2; p++) {
        u64 u2[15];
        {
            const ulonglong2* W = (const ulonglong2*)(s_w + 688);
            const u64* Bv = (const u64*)(s_w + 928);
#pragma unroll
            for (int o = 0; o < 15; o++) {
                ulonglong2 q0 = W[4*o], q1 = W[4*o+1], q2 = W[4*o+2], q3 = W[4*o+3];
                u64 A = Bv[o];
                A = ffma2(q0.x, a2[p][0], A);
                A = ffma2(q0.y, a2[p][1], A);
                A = ffma2(q1.x, a2[p][2], A);
                A = ffma2(q1.y, a2[p][3], A);
                A = ffma2(q2.x, a2[p][4], A);
                A = ffma2(q2.y, a2[p][5], A);
                A = ffma2(q3.x, a2[p][6], A);
                A = ffma2(q3.y, a2[p][7], A);
                u2[o] = A;
            }
        }
        float ul[15], uh[15];
#pragma unroll
        for (int o = 0; o < 15; o++) upk(ul[o], uh[o], u2[o]);

#pragma unroll
        for (int h = 0; h < 2; h++) {
            const int g = 2 * p + h;          // point group index 0..3
            const int bufi = g & 1;
            const float* u = h ? uh : ul;

            if (g >= 2 && t == 0) {
                // ensure prior TMA store from this buffer finished reading SMEM
                asm volatile("cp.async.bulk.wait_group.read 1;" ::: "memory");
            }
            __syncthreads();

            // Assemble 6x6 antisymmetric matrix as 9 float4s (stride 36: conflict-free STS.128)
            float4* so = (float4*)(s_o[bufi] + t * 36);
            so[0] = make_float4( 0.0f,  u[0],   u[1],   u[2]);
            so[1] = make_float4( u[3],  u[4],  -u[0],   0.0f);
            so[2] = make_float4( u[5],  u[6],   u[7],   u[8]);
            so[3] = make_float4(-u[1], -u[5],   0.0f,   u[9]);
            so[4] = make_float4( u[10], u[11], -u[2],  -u[6]);
            so[5] = make_float4(-u[9],  0.0f,   u[12],  u[13]);
            so[6] = make_float4(-u[3], -u[7],  -u[10], -u[12]);
            so[7] = make_float4( 0.0f,  u[14], -u[4],  -u[8]);
            so[8] = make_float4(-u[11],-u[13], -u[14],  0.0f);
            __syncthreads();

            int gb = base + g * TPB;
            int cg = npts - gb;
            if (cg > TPB) cg = TPB;
            if (t == 0 && cg > 0) {
                asm volatile("fence.proxy.async.shared::cta;" ::: "memory");
                unsigned saddr = (unsigned)__cvta_generic_to_shared(s_o[bufi]);
                asm volatile(
                    "cp.async.bulk.global.shared::cta.bulk_group [%0], [%1], %2;"
                    :: "l"(out + (size_t)gb * 36), "r"(saddr), "r"(cg * 144)
                    : "memory");
                asm volatile("cp.async.bulk.commit_group;" ::: "memory");
            }
        }
    }

    // flush outstanding bulk stores before exit
    if (t == 0) {
        asm volatile("cp.async.bulk.wait_group 0;" ::: "memory");
    }
}

extern "C" void kernel_launch(void* const* d_in, const int* in_sizes, int n_in,
                              void* d_out, int out_size) {
    const float* x    = (const float*)d_in[0];
    const float* Win  = (const float*)d_in[1];
    const float* bin  = (const float*)d_in[2];
    const float* W1   = (const float*)d_in[3];
    const float* b1   = (const float*)d_in[4];
    const float* W2   = (const float*)d_in[5];
    const float* b2   = (const float*)d_in[6];
    const float* W3   = (const float*)d_in[7];
    const float* b3   = (const float*)d_in[8];
    const float* W4   = (const float*)d_in[9];
    const float* b4   = (const float*)d_in[10];
    const float* Wout = (const float*)d_in[11];
    const float* bout = (const float*)d_in[12];
    float* out = (float*)d_out;

    int npts = in_sizes[0] / 6;
    int ptsPerBlock = TPB * PPT;
    int blocks = (npts + ptsPerBlock - 1) / ptsPerBlock;
    poisson_bivector_kernel<<<blocks, TPB>>>(
        x, Win, bin, W1, b1, W2, b2, W3, b3, W4, b4, Wout, bout, out, npts);
}